// round 5
// baseline (speedup 1.0000x reference)
#include <cuda_runtime.h>
#include <math.h>

#define NFRAMES 16
#define IMG_H   480
#define IMG_W   640
#define NCH     20
#define PLANE   (IMG_H * IMG_W)
#define DS_H    120
#define DS_W    160
#define NPIX    (DS_H * DS_W)
#define VR      100
#define CELLS   (VR * VR)
#define NSEM    16
#define NOUT    (2 + NSEM)
#define CPC     20          // floats per cell in acc (5 float4 groups)
#define NGRP    5
#define MIN_MAPPED 13
#define MAX_MAPPED 25

// AoS accumulator: per cell 5 float4: [g0..g3]=16 sem sums, [g4]=(obstacle-dilated, explored, pad, pad).
// Statically zero-initialized; finalize restores zeros each launch (invariant).
__device__ float4 g_acc4[NFRAMES * CELLS * NGRP];

__device__ __forceinline__ void red_v4(float4* addr, float a, float b, float c, float d) {
    asm volatile("red.global.add.v4.f32 [%0], {%1, %2, %3, %4};"
                 :: "l"(addr), "f"(a), "f"(b), "f"(c), "f"(d) : "memory");
}

__global__ void scatter_kernel(const float* __restrict__ obs, float f_pix) {
    int idx = blockIdx.x * blockDim.x + threadIdx.x;
    if (idx >= NFRAMES * NPIX) return;
    int f   = idx / NPIX;
    int pix = idx - f * NPIX;
    int row = pix / DS_W;
    int col = pix - row * DS_W;

    const float* base = obs + (size_t)f * NCH * PLANE;
    int poff = (row * 4) * IMG_W + col * 4;

    float depth = __ldg(&base[3 * PLANE + poff]);
    if (!(depth > 20.0f && depth < 500.0f)) return;

    float uu = (float)(col * 4);
    float vv = (float)(row * 4);

    // Bit-exact binning: keep true divides (bin flips would be O(1) errors)
    float X  = __fdiv_rn((uu - 320.0f) * depth, f_pix);
    float Zh = 88.0f + __fdiv_rn((240.0f - vv) * depth, f_pix);

    int xb = __float2int_rn(__fdiv_rn(X, 5.0f) + 50.0f);
    int yb = __float2int_rn(__fdiv_rn(depth, 5.0f));
    int zb = __float2int_rn(__fdiv_rn(Zh, 5.0f)) + 8;

    if (xb < 0 || xb >= VR || yb < 0 || yb >= VR || zb < 0 || zb >= 80) return;

    int cell = yb * VR + xb;
    float* accf = (float*)g_acc4;

    // Batch all 16 semantic plane loads (max MLP) before the atomics
    float s[NSEM];
    #pragma unroll
    for (int c = 0; c < NSEM; c++)
        s[c] = __ldg(&base[(4 + c) * PLANE + poff]);

    // explored indicator: idempotent plain store (group 4, lane .y)
    accf[((size_t)f * CELLS + cell) * CPC + 17] = 1.0f;

    // obstacle: write dilated (3x3, clamped) indicator directly — idempotent (group 4, lane .x)
    if (zb >= MIN_MAPPED && zb < MAX_MAPPED) {
        int y0 = yb > 0 ? yb - 1 : 0, y1 = yb < VR - 1 ? yb + 1 : VR - 1;
        int x0 = xb > 0 ? xb - 1 : 0, x1 = xb < VR - 1 ? xb + 1 : VR - 1;
        for (int yy = y0; yy <= y1; yy++)
            for (int xx = x0; xx <= x1; xx++)
                accf[((size_t)f * CELLS + yy * VR + xx) * CPC + 16] = 1.0f;
    }

    // 16 semantic adds as 4 vector reductions
    float4* c4 = g_acc4 + ((size_t)f * CELLS + cell) * NGRP;
    red_v4(c4 + 0, s[0],  s[1],  s[2],  s[3]);
    red_v4(c4 + 1, s[4],  s[5],  s[6],  s[7]);
    red_v4(c4 + 2, s[8],  s[9],  s[10], s[11]);
    red_v4(c4 + 3, s[12], s[13], s[14], s[15]);
}

// One thread per (group, frame, cell): 5x parallelism of the per-cell version.
// g-major indexing keeps warps on consecutive cells => coalesced planar stores.
__global__ void __launch_bounds__(256) finalize_kernel(float* __restrict__ out) {
    int idx = blockIdx.x * blockDim.x + threadIdx.x;
    const int PER_G = NFRAMES * CELLS;
    if (idx >= NGRP * PER_G) return;
    int g    = idx / PER_G;
    int rem  = idx - g * PER_G;
    int f    = rem / CELLS;
    int cell = rem - f * CELLS;

    float4* c4 = g_acc4 + ((size_t)f * CELLS + cell) * NGRP + g;
    float4 v = *c4;

    float* dst = out + (size_t)f * NOUT * CELLS + cell;
    if (g == 4) {
        dst[0]     = v.x;   // obstacle (already dilated, {0,1})
        dst[CELLS] = v.y;   // explored (EXP_T=1 -> identity)
    } else {
        float* d = dst + (2 + 4 * g) * CELLS;
        // x*0.2f differs from x/5 by <=1 ULP; output-only, far under 1e-3 tol
        d[0]         = fminf(fmaxf(__fmul_rn(v.x, 0.2f), 0.0f), 1.0f);
        d[CELLS]     = fminf(fmaxf(__fmul_rn(v.y, 0.2f), 0.0f), 1.0f);
        d[2 * CELLS] = fminf(fmaxf(__fmul_rn(v.z, 0.2f), 0.0f), 1.0f);
        d[3 * CELLS] = fminf(fmaxf(__fmul_rn(v.w, 0.2f), 0.0f), 1.0f);
    }

    // Reset own group for next launch (race-free)
    *c4 = make_float4(0.f, 0.f, 0.f, 0.f);
}

extern "C" void kernel_launch(void* const* d_in, const int* in_sizes, int n_in,
                              void* d_out, int out_size) {
    const float* obs = (const float*)d_in[0];   // (4,4,20,480,640) f32
    float* out = (float*)d_out;                 // (4,4,18,100,100) f32

    float f_pix = (float)(320.0 / tan(39.5 * 3.14159265358979323846 / 180.0));

    scatter_kernel<<<(NFRAMES * NPIX + 255) / 256, 256>>>(obs, f_pix);
    finalize_kernel<<<(NGRP * NFRAMES * CELLS + 255) / 256, 256>>>(out);
}